// round 14
// baseline (speedup 1.0000x reference)
#include <cuda_runtime.h>
#include <cuda_bf16.h>
#include <cstdint>

#define DIM      1024
#define D_INNER  2048
#define NHEADS   16
#define HEADDIM  128
#define D_STATE  64
#define D_PROJ   4240   // 2*D_INNER + 2*D_STATE + NHEADS
#define B_SZ     8
#define T_SZ     1024
#define M_TOK    (B_SZ * T_SZ)   // 8192
#define NBH      (B_SZ * NHEADS) // 128
#define CHUNK    64
#define NCHUNK   (T_SZ / CHUNK)  // 16

// ---------------------------------------------------------------------------
// Scratch (no cudaMalloc allowed): device globals.
// ---------------------------------------------------------------------------
__device__ float g_ys[(size_t)M_TOK * D_INNER];            // final gated ys (tf32)
__device__ float g_xr[(size_t)M_TOK * DIM];                // x tf32-rounded
__device__ float g_wir[(size_t)D_PROJ * DIM];              // W_in rounded
__device__ float g_wor[(size_t)DIM * D_INNER];             // W_out rounded
__device__ float g_xst[(size_t)NBH * T_SZ * HEADDIM];      // silu(x_p) [bh,t,p]
__device__ float g_zt [(size_t)NBH * T_SZ * HEADDIM];      // z [bh,t,p]
__device__ float g_Bc [(size_t)M_TOK * D_STATE];           // [bt,n]
__device__ float g_Cc [(size_t)M_TOK * D_STATE];           // [bt,n]
__device__ float g_ldec[(size_t)M_TOK * NHEADS];           // log(sigmoid(dt+bias)) [bt,h]
__device__ float g_yint[(size_t)NBH * HEADDIM * T_SZ];     // intra-chunk Y TRANSPOSED [bh,p,t]
__device__ float g_dH [(size_t)NBH * NCHUNK * HEADDIM * D_STATE]; // per-chunk state delta
__device__ float g_lcum[(size_t)NBH * T_SZ];               // within-chunk log-decay cumsum

// ---------------------------------------------------------------------------
// helpers
// ---------------------------------------------------------------------------
__device__ __forceinline__ uint32_t f2tf32(float f) {
    uint32_t u;
    asm("cvt.rna.tf32.f32 %0, %1;" : "=r"(u) : "f"(f));
    return u;
}
__device__ __forceinline__ float f2tf32f(float f) {
    return __uint_as_float(f2tf32(f));
}

__device__ __forceinline__ void cpasync16(uint32_t dst, const void* src) {
    asm volatile("cp.async.cg.shared.global [%0], [%1], 16;" :: "r"(dst), "l"(src));
}

__device__ __forceinline__ void mma_tf32(float* c, const uint32_t* a,
                                         uint32_t b0, uint32_t b1) {
    asm volatile(
        "mma.sync.aligned.m16n8k8.row.col.f32.tf32.tf32.f32 "
        "{%0,%1,%2,%3}, {%4,%5,%6,%7}, {%8,%9}, {%0,%1,%2,%3};"
        : "+f"(c[0]), "+f"(c[1]), "+f"(c[2]), "+f"(c[3])
        : "r"(a[0]), "r"(a[1]), "r"(a[2]), "r"(a[3]), "r"(b0), "r"(b1));
}

// ldmatrix: one instr loads 4 (x4) or 2 (x2) 8x8-b16 tiles == tf32 fragments
__device__ __forceinline__ void ldsm_x4(uint32_t* r, uint32_t addr) {
    asm volatile("ldmatrix.sync.aligned.m8n8.x4.shared.b16 {%0,%1,%2,%3}, [%4];"
                 : "=r"(r[0]), "=r"(r[1]), "=r"(r[2]), "=r"(r[3]) : "r"(addr));
}
__device__ __forceinline__ void ldsm_x2(uint32_t* r, uint32_t addr) {
    asm volatile("ldmatrix.sync.aligned.m8n8.x2.shared.b16 {%0,%1}, [%2];"
                 : "=r"(r[0]), "=r"(r[1]) : "r"(addr));
}

// one launch rounding all three GEMM inputs fp32 -> tf32-bits
__global__ void round_all(const float* __restrict__ s0, float* __restrict__ d0, int n0,
                          const float* __restrict__ s1, float* __restrict__ d1, int n1,
                          const float* __restrict__ s2, float* __restrict__ d2, int n2) {
    const int stride = gridDim.x * blockDim.x;
    const int t0 = blockIdx.x * blockDim.x + threadIdx.x;
    for (int i = t0; i < n0; i += stride) d0[i] = __uint_as_float(f2tf32(s0[i]));
    for (int i = t0; i < n1; i += stride) d1[i] = __uint_as_float(f2tf32(s1[i]));
    for (int i = t0; i < n2; i += stride) d2[i] = __uint_as_float(f2tf32(s2[i]));
}

// ---------------------------------------------------------------------------
// scatter epilogue for GEMM1 (mode 1): route proj columns to scan buffers.
// ---------------------------------------------------------------------------
__device__ __forceinline__ void scatter_pair(int row, int col, float v0, float v1,
                                             const float* __restrict__ dt_bias)
{
    const int b = row >> 10;
    const int t = row & 1023;
    if (col < D_INNER) {                        // x -> silu -> g_xst [bh,t,p]
        const int h = col >> 7, pp = col & 127;
        const float s0 = v0 / (1.f + __expf(-v0));
        const float s1 = v1 / (1.f + __expf(-v1));
        *(float2*)(g_xst + ((size_t)(b * NHEADS + h) * T_SZ + t) * HEADDIM + pp)
            = make_float2(s0, s1);
    } else if (col < 2 * D_INNER) {             // z -> g_zt [bh,t,p]
        const int c = col - D_INNER;
        const int h = c >> 7, pp = c & 127;
        *(float2*)(g_zt + ((size_t)(b * NHEADS + h) * T_SZ + t) * HEADDIM + pp)
            = make_float2(v0, v1);
    } else if (col < 2 * D_INNER + D_STATE) {   // B
        *(float2*)(g_Bc + (size_t)row * D_STATE + (col - 2 * D_INNER))
            = make_float2(v0, v1);
    } else if (col < 2 * D_INNER + 2 * D_STATE) { // C
        *(float2*)(g_Cc + (size_t)row * D_STATE + (col - 2 * D_INNER - D_STATE))
            = make_float2(v0, v1);
    } else {                                    // dt -> log(sigmoid(dt+bias))
        const int h = col - (2 * D_INNER + 2 * D_STATE);
        const float u0 = v0 + dt_bias[h];
        const float u1 = v1 + dt_bias[h + 1];
        g_ldec[(size_t)row * NHEADS + h]     = (u0 > -15.f) ? -log1pf(__expf(-u0)) : u0;
        g_ldec[(size_t)row * NHEADS + h + 1] = (u1 > -15.f) ? -log1pf(__expf(-u1)) : u1;
    }
}

// ---------------------------------------------------------------------------
// tf32 mma.sync GEMM (R6 tiling + ldmatrix fragment loads; unchanged from R12)
// ---------------------------------------------------------------------------
#define GSMEM_BYTES 98304

__global__ void __launch_bounds__(256, 2)
gemm_tf32(const float* __restrict__ A, const float* __restrict__ W,
          float* __restrict__ C, int M, int N, int K,
          int bnOff, int mode, const float* __restrict__ dt_bias)
{
    extern __shared__ float smem[];
    const uint32_t smemAddr = (uint32_t)__cvta_generic_to_shared(smem);

    const int tid  = threadIdx.x;
    const int lane = tid & 31;
    const int wid  = tid >> 5;
    const int wm   = wid & 1;
    const int wn   = wid >> 1;

    const int bm = blockIdx.y * 128;
    const int bn = blockIdx.x * 128 + bnOff;

    const int sr   = tid >> 1;
    const int half = tid & 1;
    const float* arow = A + (size_t)(bm + sr) * K;
    const int wRow = (bn + sr) < N ? (bn + sr) : (N - 1);
    const float* wrow = W + (size_t)wRow * K;

    const int g      = lane >> 3;
    const int rIn    = lane & 7;
    const int khalfA = g >> 1;
    const int khalfB = g & 1;
    uint32_t aOff[4], aSw[4], bOff[4], bSw[4];
#pragma unroll
    for (int mt = 0; mt < 4; mt++) {
        const int r = wm * 64 + mt * 16 + (g & 1) * 8 + rIn;
        aOff[mt] = r * 128;
        aSw[mt]  = r & 7;
    }
#pragma unroll
    for (int nt = 0; nt < 4; nt++) {
        const int r = wn * 32 + nt * 8 + rIn;
        bOff[nt] = 16384 + r * 128;
        bSw[nt]  = r & 7;
    }

    float acc[4][4][4];
#pragma unroll
    for (int mt = 0; mt < 4; mt++)
#pragma unroll
        for (int nt = 0; nt < 4; nt++)
#pragma unroll
            for (int r = 0; r < 4; r++) acc[mt][nt][r] = 0.f;

    const int nk = K >> 5;

#define STAGE(bufIdx, kk)                                                     \
    do {                                                                      \
        uint32_t baseA = smemAddr + (bufIdx) * 32768 + sr * 128;              \
        uint32_t baseB = baseA + 16384;                                       \
        _Pragma("unroll")                                                     \
        for (int i = 0; i < 4; i++) {                                         \
            int ch  = half * 4 + i;                                           \
            int chs = ch ^ (sr & 7);                                          \
            cpasync16(baseA + chs * 16, arow + (kk) + ch * 4);                \
            cpasync16(baseB + chs * 16, wrow + (kk) + ch * 4);                \
        }                                                                     \
    } while (0)

    STAGE(0, 0);
    asm volatile("cp.async.commit_group;");
    if (nk > 1) STAGE(1, 32);
    asm volatile("cp.async.commit_group;");

    int bufC = 0, bufP = 2;
    for (int kt = 0; kt < nk; kt++) {
        if (kt + 2 < nk) STAGE(bufP, (kt + 2) * 32);
        asm volatile("cp.async.commit_group;");
        asm volatile("cp.async.wait_group 2;");
        __syncthreads();

        const uint32_t stageBase = smemAddr + bufC * 32768;

#pragma unroll
        for (int ks = 0; ks < 4; ks++) {
            uint32_t af[4][4], bf[4][2];
#pragma unroll
            for (int mt = 0; mt < 4; mt++) {
                const uint32_t ch = (uint32_t)(ks * 2 + khalfA) ^ aSw[mt];
                ldsm_x4(af[mt], stageBase + aOff[mt] + ch * 16);
            }
#pragma unroll
            for (int nt = 0; nt < 4; nt++) {
                const uint32_t ch = (uint32_t)(ks * 2 + khalfB) ^ bSw[nt];
                ldsm_x2(bf[nt], stageBase + bOff[nt] + ch * 16);
            }
#pragma unroll
            for (int mt = 0; mt < 4; mt++)
#pragma unroll
                for (int nt = 0; nt < 4; nt++)
                    mma_tf32(acc[mt][nt], af[mt], bf[nt][0], bf[nt][1]);
        }
        __syncthreads();
        bufC = (bufC == 2) ? 0 : bufC + 1;
        bufP = (bufP == 2) ? 0 : bufP + 1;
    }
#undef STAGE

#pragma unroll
    for (int mt = 0; mt < 4; mt++) {
        const int row0 = bm + wm * 64 + mt * 16 + (lane >> 2);
#pragma unroll
        for (int nt = 0; nt < 4; nt++) {
            const int col = bn + wn * 32 + nt * 8 + (lane & 3) * 2;
            if (col < N) {
                if (mode == 0) {
                    *(float2*)(C + (size_t)row0 * N + col)
                        = make_float2(acc[mt][nt][0], acc[mt][nt][1]);
                    *(float2*)(C + (size_t)(row0 + 8) * N + col)
                        = make_float2(acc[mt][nt][2], acc[mt][nt][3]);
                } else {
                    scatter_pair(row0,     col, acc[mt][nt][0], acc[mt][nt][1], dt_bias);
                    scatter_pair(row0 + 8, col, acc[mt][nt][2], acc[mt][nt][3], dt_bias);
                }
            }
        }
    }
}

// ---------------------------------------------------------------------------
// Pass 1 (TENSORIZED, unchanged from R8): one block per (bh, chunk) = 2048.
// ---------------------------------------------------------------------------
__global__ void __launch_bounds__(256)
chunk_intra()
{
    extern __shared__ float sm[];
    float* sXsT = sm;                    // [128][68]  Xs^T[p][s]
    float* sC   = sXsT + 128 * 68;       // [64][68]   C[t][n]
    float* sB   = sC   + 64 * 68;        // [64][68]   B[s][n]   (rounded)
    float* sBT  = sB   + 64 * 68;        // [64][68]   B^T[n][s]
    float* sG   = sBT  + 64 * 68;        // [64][68]   G[t][s]
    float* sLc  = sG   + 64 * 68;        // [64]
    float* sW   = sLc  + 64;             // [64]

    const int blk  = blockIdx.x;
    const int bh   = blk >> 4;
    const int c    = blk & 15;
    const int b    = bh >> 4;
    const int h    = bh & 15;
    const int tid  = threadIdx.x;
    const int lane = tid & 31;
    const int wid  = tid >> 5;

    const int tglob = b * T_SZ + c * CHUNK;
    const size_t xbase = ((size_t)bh * T_SZ + c * CHUNK) * HEADDIM;

    if (tid < 64)
        sLc[tid] = g_ldec[(size_t)(tglob + tid) * NHEADS + h];
    for (int i = tid; i < CHUNK * HEADDIM; i += 256) {
        const int s = i >> 7, p = i & 127;
        sXsT[p * 68 + s] = f2tf32f(g_xst[xbase + i]);
    }
    for (int i = tid; i < 4096; i += 256) {
        const int s = i >> 6, n = i & 63;
        const float bv = g_Bc[(size_t)(tglob + s) * D_STATE + n];
        const float cv = g_Cc[(size_t)(tglob + s) * D_STATE + n];
        sB [s * 68 + n] = f2tf32f(bv);
        sBT[n * 68 + s] = bv;
        sC [s * 68 + n] = f2tf32f(cv);
    }
    __syncthreads();

    if (wid == 0) {
        const float e0 = sLc[2 * lane], e1 = sLc[2 * lane + 1];
        float v = e0 + e1;
#pragma unroll
        for (int ofs = 1; ofs < 32; ofs <<= 1) {
            const float o = __shfl_up_sync(0xffffffffu, v, ofs);
            if (lane >= ofs) v += o;
        }
        sLc[2 * lane]     = v - e1;
        sLc[2 * lane + 1] = v;
    }

    const uint32_t* uXsT = (const uint32_t*)sXsT;
    const uint32_t* uC   = (const uint32_t*)sC;
    const uint32_t* uB   = (const uint32_t*)sB;
    const uint32_t* uBT  = (const uint32_t*)sBT;
    const uint32_t* uG   = (const uint32_t*)sG;

    float accS[2][2][4];
#pragma unroll
    for (int mt = 0; mt < 2; mt++)
#pragma unroll
        for (int nt = 0; nt < 2; nt++)
#pragma unroll
            for (int r = 0; r < 4; r++) accS[mt][nt][r] = 0.f;

    const int smb = (wid & 1) * 32;
    const int snb = (wid >> 1) * 16;
#pragma unroll
    for (int ks = 0; ks < 8; ks++) {
        const int kc = ks * 8 + (lane & 3);
        uint32_t af[2][4];
#pragma unroll
        for (int mt = 0; mt < 2; mt++) {
            const int r = smb + mt * 16 + (lane >> 2);
            af[mt][0] = uC[r * 68 + kc];
            af[mt][1] = uC[(r + 8) * 68 + kc];
            af[mt][2] = uC[r * 68 + kc + 4];
            af[mt][3] = uC[(r + 8) * 68 + kc + 4];
        }
#pragma unroll
        for (int nt = 0; nt < 2; nt++) {
            const int rn = snb + nt * 8 + (lane >> 2);
            const uint32_t b0 = uB[rn * 68 + kc];
            const uint32_t b1 = uB[rn * 68 + kc + 4];
#pragma unroll
            for (int mt = 0; mt < 2; mt++)
                mma_tf32(accS[mt][nt], af[mt], b0, b1);
        }
    }
    __syncthreads();

#pragma unroll
    for (int mt = 0; mt < 2; mt++)
#pragma unroll
        for (int nt = 0; nt < 2; nt++)
#pragma unroll
            for (int r = 0; r < 4; r++) {
                const int t = smb + mt * 16 + (lane >> 2) + ((r >> 1) ? 8 : 0);
                const int s = snb + nt * 8 + (lane & 3) * 2 + (r & 1);
                const float gg = (s <= t)
                    ? __expf(sLc[t] - sLc[s]) * accS[mt][nt][r] : 0.f;
                sG[t * 68 + s] = f2tf32f(gg);
            }
    if (tid < 64) {
        sW[tid] = __expf(sLc[63] - sLc[tid]);
        g_lcum[(size_t)bh * T_SZ + c * CHUNK + tid] = sLc[tid];
    }
    __syncthreads();

    for (int i = tid; i < 4096; i += 256) {
        const int n = i >> 6, s = i & 63;
        sBT[n * 68 + s] = f2tf32f(sBT[n * 68 + s] * sW[s]);
    }
    __syncthreads();

    float accY[2][4][4], accH[2][4][4];
#pragma unroll
    for (int mt = 0; mt < 2; mt++)
#pragma unroll
        for (int nt = 0; nt < 4; nt++)
#pragma unroll
            for (int r = 0; r < 4; r++) { accY[mt][nt][r] = 0.f; accH[mt][nt][r] = 0.f; }

    const int pb = (wid & 3) * 32;
    const int tb = (wid >> 2) * 32;
#pragma unroll
    for (int ks = 0; ks < 8; ks++) {
        const int kc = ks * 8 + (lane & 3);
        uint32_t af[2][4];
#pragma unroll
        for (int mt = 0; mt < 2; mt++) {
            const int r = pb + mt * 16 + (lane >> 2);
            af[mt][0] = uXsT[r * 68 + kc];
            af[mt][1] = uXsT[(r + 8) * 68 + kc];
            af[mt][2] = uXsT[r * 68 + kc + 4];
            af[mt][3] = uXsT[(r + 8) * 68 + kc + 4];
        }
#pragma unroll
        for (int nt = 0; nt < 4; nt++) {
            const int rn = tb + nt * 8 + (lane >> 2);
            const uint32_t gy0 = uG [rn * 68 + kc];
            const uint32_t gy1 = uG [rn * 68 + kc + 4];
            const uint32_t bb0 = uBT[rn * 68 + kc];
            const uint32_t bb1 = uBT[rn * 68 + kc + 4];
#pragma unroll
            for (int mt = 0; mt < 2; mt++) {
                mma_tf32(accY[mt][nt], af[mt], gy0, gy1);
                mma_tf32(accH[mt][nt], af[mt], bb0, bb1);
            }
        }
    }

    const size_t hbase = ((size_t)(bh * NCHUNK + c)) * (HEADDIM * D_STATE);
#pragma unroll
    for (int mt = 0; mt < 2; mt++) {
        const int p0 = pb + mt * 16 + (lane >> 2);
#pragma unroll
        for (int nt = 0; nt < 4; nt++) {
            const int tn = tb + nt * 8 + (lane & 3) * 2;
            float* y0 = g_yint + ((size_t)bh * HEADDIM + p0) * T_SZ + c * CHUNK + tn;
            *(float2*)y0              = make_float2(accY[mt][nt][0], accY[mt][nt][1]);
            *(float2*)(y0 + 8 * T_SZ) = make_float2(accY[mt][nt][2], accY[mt][nt][3]);
            float* d0 = g_dH + hbase + (size_t)p0 * D_STATE + tn;
            *(float2*)d0                 = make_float2(accH[mt][nt][0], accH[mt][nt][1]);
            *(float2*)(d0 + 8 * D_STATE) = make_float2(accH[mt][nt][2], accH[mt][nt][3]);
        }
    }
}

// ---------------------------------------------------------------------------
// FUSED state + inter, p-PARTITIONED: 4 blocks per bh (512 blocks x 256 thr).
// Each block owns p-rows [q*32, q*32+32): H-slice resident in smem across the
// 16-chunk loop. Per chunk: Y_inter from pre-update slice (same n-loop order
// as R12 inter), gate, write ys; then slice = a*slice + dH. Bit-identical math;
// g_Hc round-trip eliminated WITHOUT the R13 occupancy collapse.
// ---------------------------------------------------------------------------
__global__ void __launch_bounds__(256)
state_inter_split(const float* __restrict__ H0, float* __restrict__ ys,
                  float* __restrict__ Hout, int writeH)
{
    __shared__ float sH [32 * 65];
    __shared__ float sC3[64 * 65];
    __shared__ float sP [64];

    const int bh  = blockIdx.x >> 2;
    const int q   = blockIdx.x & 3;
    const int p0  = q * 32;
    const int b   = bh >> 4;
    const int h   = bh & 15;
    const int tid = threadIdx.x;
    const int tx  = tid & 15;   // t tile (4 each)
    const int ty  = tid >> 4;   // 0..15 -> 2 p-rows each

    // load H0 slice
    for (int i = tid; i < 2048; i += 256) {
        const int p = i >> 6, n = i & 63;
        sH[p * 65 + n] = H0[(size_t)bh * (HEADDIM * D_STATE) + (p0 + p) * D_STATE + n];
    }
    __syncthreads();

    for (int c = 0; c < NCHUNK; c++) {
        const int tglob = b * T_SZ + c * CHUNK;

        for (int i = tid; i < 4096; i += 256) {
            const int s = i >> 6, n = i & 63;
            sC3[s * 65 + n] = g_Cc[(size_t)(tglob + s) * D_STATE + n];
        }
        if (tid < 64)
            sP[tid] = __expf(g_lcum[(size_t)bh * T_SZ + c * CHUNK + tid]);
        __syncthreads();

        // Y_inter from pre-update H slice
        float acc[2][4];
#pragma unroll
        for (int i = 0; i < 2; i++)
#pragma unroll
            for (int j = 0; j < 4; j++) acc[i][j] = 0.f;

        for (int n = 0; n < 64; n++) {
            float hr[2], cr[4];
#pragma unroll
            for (int i = 0; i < 2; i++) hr[i] = sH[(ty * 2 + i) * 65 + n];
#pragma unroll
            for (int j = 0; j < 4; j++) cr[j] = sC3[(tx * 4 + j) * 65 + n];
#pragma unroll
            for (int i = 0; i < 2; i++)
#pragma unroll
                for (int j = 0; j < 4; j++) acc[i][j] += hr[i] * cr[j];
        }

        float4 yr[2];
#pragma unroll
        for (int i = 0; i < 2; i++)
            yr[i] = *(const float4*)(g_yint
                     + ((size_t)bh * HEADDIM + p0 + ty * 2 + i) * T_SZ
                     + c * CHUNK + tx * 4);

#pragma unroll
        for (int j = 0; j < 4; j++) {
            const int tl = tx * 4 + j;
            const size_t trow = (size_t)bh * T_SZ + c * CHUNK + tl;
            const float P = sP[tl];
            float2 z = *(const float2*)(g_zt + trow * HEADDIM + p0 + ty * 2);
            const float zv[2] = { z.x, z.y };
            uint32_t ov[2];
#pragma unroll
            for (int i = 0; i < 2; i++) {
                const float yintra = ((const float*)&yr[i])[j];
                const float y  = yintra + P * acc[i][j];
                const float zy = zv[i] + y;
                ov[i] = f2tf32(y * (zy / (1.f + __expf(-zy))));
            }
            *(float2*)(ys + ((size_t)(b * T_SZ + c * CHUNK + tl)) * D_INNER
                       + h * HEADDIM + p0 + ty * 2)
                = make_float2(__uint_as_float(ov[0]), __uint_as_float(ov[1]));
        }
        __syncthreads();   // Y reads of sH done before update

        // H = a*H + dH[c]  (slice)
        const float a = __expf(g_lcum[(size_t)bh * T_SZ + c * CHUNK + 63]);
        const float* dh = g_dH + ((size_t)(bh * NCHUNK + c)) * (HEADDIM * D_STATE)
                          + (size_t)p0 * D_STATE;
        for (int i = tid; i < 2048; i += 256) {
            const int p = i >> 6, n = i & 63;
            sH[p * 65 + n] = a * sH[p * 65 + n] + dh[i];
        }
        __syncthreads();
    }

    if (writeH) {
        for (int i = tid; i < 2048; i += 256) {
            const int p = i >> 6, n = i & 63;
            Hout[(size_t)bh * (HEADDIM * D_STATE) + (p0 + p) * D_STATE + n]
                = sH[p * 65 + n];
        }
    }
}

// ---------------------------------------------------------------------------
extern "C" void kernel_launch(void* const* d_in, const int* in_sizes, int n_in,
                              void* d_out, int out_size)
{
    const float* x       = (const float*)d_in[0];
    const float* H0      = (const float*)d_in[1];
    const float* W_in    = (const float*)d_in[2];
    const float* W_out   = (const float*)d_in[3];
    const float* dt_bias = (const float*)d_in[4];
    float* out = (float*)d_out;

    static float *ys_p = nullptr, *xr_p = nullptr, *wir_p = nullptr, *wor_p = nullptr;
    if (!ys_p) {
        cudaGetSymbolAddress((void**)&ys_p,  g_ys);
        cudaGetSymbolAddress((void**)&xr_p,  g_xr);
        cudaGetSymbolAddress((void**)&wir_p, g_wir);
        cudaGetSymbolAddress((void**)&wor_p, g_wor);
        cudaFuncSetAttribute(gemm_tf32,
                             cudaFuncAttributeMaxDynamicSharedMemorySize, GSMEM_BYTES);
        cudaFuncSetAttribute(chunk_intra,
                             cudaFuncAttributeMaxDynamicSharedMemorySize, 104960);
    }

    const int out_elems = B_SZ * T_SZ * DIM;
    const int h_elems   = B_SZ * NHEADS * HEADDIM * D_STATE;
    const int writeH    = (out_size >= out_elems + h_elems) ? 1 : 0;
    float* Hout = out + out_elems;

    // 0) tf32-round all GEMM inputs (one launch)
    round_all<<<2048, 256>>>(x, xr_p, M_TOK * DIM,
                             W_in, wir_p, D_PROJ * DIM,
                             W_out, wor_p, DIM * D_INNER);

    // 1) proj GEMM with fused scatter epilogue
    gemm_tf32<<<dim3((D_PROJ + 127) / 128, M_TOK / 128), 256, GSMEM_BYTES>>>(
        xr_p, wir_p, nullptr, M_TOK, D_PROJ, DIM, 0, 1, dt_bias);

    // 2) chunked scan: intra, then p-partitioned fused state+inter
    chunk_intra<<<NBH * NCHUNK, 256, 104960>>>();
    state_inter_split<<<NBH * 4, 256>>>(H0, ys_p, Hout, writeH);

    // 3) output = ys @ W_out^T
    gemm_tf32<<<dim3(DIM / 128, M_TOK / 128), 256, GSMEM_BYTES>>>(
        ys_p, wor_p, out, M_TOK, DIM, D_INNER, 0, 0, nullptr);
}

// round 15
// speedup vs baseline: 1.0595x; 1.0595x over previous
#include <cuda_runtime.h>
#include <cuda_bf16.h>
#include <cstdint>

#define DIM      1024
#define D_INNER  2048
#define NHEADS   16
#define HEADDIM  128
#define D_STATE  64
#define D_PROJ   4240   // 2*D_INNER + 2*D_STATE + NHEADS
#define B_SZ     8
#define T_SZ     1024
#define M_TOK    (B_SZ * T_SZ)   // 8192
#define NBH      (B_SZ * NHEADS) // 128
#define CHUNK    64
#define NCHUNK   (T_SZ / CHUNK)  // 16

// ---------------------------------------------------------------------------
// Scratch (no cudaMalloc allowed): device globals.
// ---------------------------------------------------------------------------
__device__ float g_ys[(size_t)M_TOK * D_INNER];            // final gated ys (tf32)
__device__ float g_xr[(size_t)M_TOK * DIM];                // x tf32-rounded
__device__ float g_wir[(size_t)D_PROJ * DIM];              // W_in rounded
__device__ float g_wor[(size_t)DIM * D_INNER];             // W_out rounded
__device__ float g_xst[(size_t)NBH * T_SZ * HEADDIM];      // silu(x_p) [bh,t,p]
__device__ float g_zt [(size_t)NBH * T_SZ * HEADDIM];      // z [bh,t,p]
__device__ float g_Bc [(size_t)M_TOK * D_STATE];           // [bt,n]
__device__ float g_Cc [(size_t)M_TOK * D_STATE];           // [bt,n]
__device__ float g_ldec[(size_t)M_TOK * NHEADS];           // log(sigmoid(dt+bias)) [bt,h]
__device__ float g_yint[(size_t)NBH * HEADDIM * T_SZ];     // intra-chunk Y TRANSPOSED [bh,p,t]
__device__ float g_dH [(size_t)NBH * NCHUNK * HEADDIM * D_STATE]; // per-chunk state delta
__device__ float g_Hc [(size_t)NBH * NCHUNK * HEADDIM * D_STATE]; // state ENTERING chunk c
__device__ float g_lcum[(size_t)NBH * T_SZ];               // within-chunk log-decay cumsum

// ---------------------------------------------------------------------------
// helpers
// ---------------------------------------------------------------------------
__device__ __forceinline__ uint32_t f2tf32(float f) {
    uint32_t u;
    asm("cvt.rna.tf32.f32 %0, %1;" : "=r"(u) : "f"(f));
    return u;
}
__device__ __forceinline__ float f2tf32f(float f) {
    return __uint_as_float(f2tf32(f));
}

__device__ __forceinline__ void cpasync16(uint32_t dst, const void* src) {
    asm volatile("cp.async.cg.shared.global [%0], [%1], 16;" :: "r"(dst), "l"(src));
}

__device__ __forceinline__ void mma_tf32(float* c, const uint32_t* a,
                                         uint32_t b0, uint32_t b1) {
    asm volatile(
        "mma.sync.aligned.m16n8k8.row.col.f32.tf32.tf32.f32 "
        "{%0,%1,%2,%3}, {%4,%5,%6,%7}, {%8,%9}, {%0,%1,%2,%3};"
        : "+f"(c[0]), "+f"(c[1]), "+f"(c[2]), "+f"(c[3])
        : "r"(a[0]), "r"(a[1]), "r"(a[2]), "r"(a[3]), "r"(b0), "r"(b1));
}

// ldmatrix: one instr loads 4 (x4) or 2 (x2) 8x8-b16 tiles == tf32 fragments
__device__ __forceinline__ void ldsm_x4(uint32_t* r, uint32_t addr) {
    asm volatile("ldmatrix.sync.aligned.m8n8.x4.shared.b16 {%0,%1,%2,%3}, [%4];"
                 : "=r"(r[0]), "=r"(r[1]), "=r"(r[2]), "=r"(r[3]) : "r"(addr));
}
__device__ __forceinline__ void ldsm_x2(uint32_t* r, uint32_t addr) {
    asm volatile("ldmatrix.sync.aligned.m8n8.x2.shared.b16 {%0,%1}, [%2];"
                 : "=r"(r[0]), "=r"(r[1]) : "r"(addr));
}

// one launch rounding all three GEMM inputs fp32 -> tf32-bits
__global__ void round_all(const float* __restrict__ s0, float* __restrict__ d0, int n0,
                          const float* __restrict__ s1, float* __restrict__ d1, int n1,
                          const float* __restrict__ s2, float* __restrict__ d2, int n2) {
    const int stride = gridDim.x * blockDim.x;
    const int t0 = blockIdx.x * blockDim.x + threadIdx.x;
    for (int i = t0; i < n0; i += stride) d0[i] = __uint_as_float(f2tf32(s0[i]));
    for (int i = t0; i < n1; i += stride) d1[i] = __uint_as_float(f2tf32(s1[i]));
    for (int i = t0; i < n2; i += stride) d2[i] = __uint_as_float(f2tf32(s2[i]));
}

// ---------------------------------------------------------------------------
// scatter epilogue for GEMM1 (mode 1): route proj columns to scan buffers.
// ---------------------------------------------------------------------------
__device__ __forceinline__ void scatter_pair(int row, int col, float v0, float v1,
                                             const float* __restrict__ dt_bias)
{
    const int b = row >> 10;
    const int t = row & 1023;
    if (col < D_INNER) {                        // x -> silu -> g_xst [bh,t,p]
        const int h = col >> 7, pp = col & 127;
        const float s0 = v0 / (1.f + __expf(-v0));
        const float s1 = v1 / (1.f + __expf(-v1));
        *(float2*)(g_xst + ((size_t)(b * NHEADS + h) * T_SZ + t) * HEADDIM + pp)
            = make_float2(s0, s1);
    } else if (col < 2 * D_INNER) {             // z -> g_zt [bh,t,p]
        const int c = col - D_INNER;
        const int h = c >> 7, pp = c & 127;
        *(float2*)(g_zt + ((size_t)(b * NHEADS + h) * T_SZ + t) * HEADDIM + pp)
            = make_float2(v0, v1);
    } else if (col < 2 * D_INNER + D_STATE) {   // B
        *(float2*)(g_Bc + (size_t)row * D_STATE + (col - 2 * D_INNER))
            = make_float2(v0, v1);
    } else if (col < 2 * D_INNER + 2 * D_STATE) { // C
        *(float2*)(g_Cc + (size_t)row * D_STATE + (col - 2 * D_INNER - D_STATE))
            = make_float2(v0, v1);
    } else {                                    // dt -> log(sigmoid(dt+bias))
        const int h = col - (2 * D_INNER + 2 * D_STATE);
        const float u0 = v0 + dt_bias[h];
        const float u1 = v1 + dt_bias[h + 1];
        g_ldec[(size_t)row * NHEADS + h]     = (u0 > -15.f) ? -log1pf(__expf(-u0)) : u0;
        g_ldec[(size_t)row * NHEADS + h + 1] = (u1 > -15.f) ? -log1pf(__expf(-u1)) : u1;
    }
}

// ---------------------------------------------------------------------------
// tf32 mma.sync GEMM (R6 tiling + ldmatrix fragment loads; exact R12 body)
// ---------------------------------------------------------------------------
#define GSMEM_BYTES 98304

__global__ void __launch_bounds__(256, 2)
gemm_tf32(const float* __restrict__ A, const float* __restrict__ W,
          float* __restrict__ C, int M, int N, int K,
          int bnOff, int mode, const float* __restrict__ dt_bias)
{
    extern __shared__ float smem[];
    const uint32_t smemAddr = (uint32_t)__cvta_generic_to_shared(smem);

    const int tid  = threadIdx.x;
    const int lane = tid & 31;
    const int wid  = tid >> 5;
    const int wm   = wid & 1;
    const int wn   = wid >> 1;

    const int bm = blockIdx.y * 128;
    const int bn = blockIdx.x * 128 + bnOff;

    const int sr   = tid >> 1;
    const int half = tid & 1;
    const float* arow = A + (size_t)(bm + sr) * K;
    const int wRow = (bn + sr) < N ? (bn + sr) : (N - 1);
    const float* wrow = W + (size_t)wRow * K;

    const int g      = lane >> 3;
    const int rIn    = lane & 7;
    const int khalfA = g >> 1;
    const int khalfB = g & 1;
    uint32_t aOff[4], aSw[4], bOff[4], bSw[4];
#pragma unroll
    for (int mt = 0; mt < 4; mt++) {
        const int r = wm * 64 + mt * 16 + (g & 1) * 8 + rIn;
        aOff[mt] = r * 128;
        aSw[mt]  = r & 7;
    }
#pragma unroll
    for (int nt = 0; nt < 4; nt++) {
        const int r = wn * 32 + nt * 8 + rIn;
        bOff[nt] = 16384 + r * 128;
        bSw[nt]  = r & 7;
    }

    float acc[4][4][4];
#pragma unroll
    for (int mt = 0; mt < 4; mt++)
#pragma unroll
        for (int nt = 0; nt < 4; nt++)
#pragma unroll
            for (int r = 0; r < 4; r++) acc[mt][nt][r] = 0.f;

    const int nk = K >> 5;

#define STAGE(bufIdx, kk)                                                     \
    do {                                                                      \
        uint32_t baseA = smemAddr + (bufIdx) * 32768 + sr * 128;              \
        uint32_t baseB = baseA + 16384;                                       \
        _Pragma("unroll")                                                     \
        for (int i = 0; i < 4; i++) {                                         \
            int ch  = half * 4 + i;                                           \
            int chs = ch ^ (sr & 7);                                          \
            cpasync16(baseA + chs * 16, arow + (kk) + ch * 4);                \
            cpasync16(baseB + chs * 16, wrow + (kk) + ch * 4);                \
        }                                                                     \
    } while (0)

    STAGE(0, 0);
    asm volatile("cp.async.commit_group;");
    if (nk > 1) STAGE(1, 32);
    asm volatile("cp.async.commit_group;");

    int bufC = 0, bufP = 2;
    for (int kt = 0; kt < nk; kt++) {
        if (kt + 2 < nk) STAGE(bufP, (kt + 2) * 32);
        asm volatile("cp.async.commit_group;");
        asm volatile("cp.async.wait_group 2;");
        __syncthreads();

        const uint32_t stageBase = smemAddr + bufC * 32768;

#pragma unroll
        for (int ks = 0; ks < 4; ks++) {
            uint32_t af[4][4], bf[4][2];
#pragma unroll
            for (int mt = 0; mt < 4; mt++) {
                const uint32_t ch = (uint32_t)(ks * 2 + khalfA) ^ aSw[mt];
                ldsm_x4(af[mt], stageBase + aOff[mt] + ch * 16);
            }
#pragma unroll
            for (int nt = 0; nt < 4; nt++) {
                const uint32_t ch = (uint32_t)(ks * 2 + khalfB) ^ bSw[nt];
                ldsm_x2(bf[nt], stageBase + bOff[nt] + ch * 16);
            }
#pragma unroll
            for (int mt = 0; mt < 4; mt++)
#pragma unroll
                for (int nt = 0; nt < 4; nt++)
                    mma_tf32(acc[mt][nt], af[mt], bf[nt][0], bf[nt][1]);
        }
        __syncthreads();
        bufC = (bufC == 2) ? 0 : bufC + 1;
        bufP = (bufP == 2) ? 0 : bufP + 1;
    }
#undef STAGE

#pragma unroll
    for (int mt = 0; mt < 4; mt++) {
        const int row0 = bm + wm * 64 + mt * 16 + (lane >> 2);
#pragma unroll
        for (int nt = 0; nt < 4; nt++) {
            const int col = bn + wn * 32 + nt * 8 + (lane & 3) * 2;
            if (col < N) {
                if (mode == 0) {
                    *(float2*)(C + (size_t)row0 * N + col)
                        = make_float2(acc[mt][nt][0], acc[mt][nt][1]);
                    *(float2*)(C + (size_t)(row0 + 8) * N + col)
                        = make_float2(acc[mt][nt][2], acc[mt][nt][3]);
                } else {
                    scatter_pair(row0,     col, acc[mt][nt][0], acc[mt][nt][1], dt_bias);
                    scatter_pair(row0 + 8, col, acc[mt][nt][2], acc[mt][nt][3], dt_bias);
                }
            }
        }
    }
}

// ---------------------------------------------------------------------------
// Pass 1 (TENSORIZED, exact R12 body): one block per (bh, chunk) = 2048.
// ---------------------------------------------------------------------------
__global__ void __launch_bounds__(256)
chunk_intra()
{
    extern __shared__ float sm[];
    float* sXsT = sm;                    // [128][68]  Xs^T[p][s]
    float* sC   = sXsT + 128 * 68;       // [64][68]   C[t][n]
    float* sB   = sC   + 64 * 68;        // [64][68]   B[s][n]   (rounded)
    float* sBT  = sB   + 64 * 68;        // [64][68]   B^T[n][s]
    float* sG   = sBT  + 64 * 68;        // [64][68]   G[t][s]
    float* sLc  = sG   + 64 * 68;        // [64]
    float* sW   = sLc  + 64;             // [64]

    const int blk  = blockIdx.x;
    const int bh   = blk >> 4;
    const int c    = blk & 15;
    const int b    = bh >> 4;
    const int h    = bh & 15;
    const int tid  = threadIdx.x;
    const int lane = tid & 31;
    const int wid  = tid >> 5;

    const int tglob = b * T_SZ + c * CHUNK;
    const size_t xbase = ((size_t)bh * T_SZ + c * CHUNK) * HEADDIM;

    if (tid < 64)
        sLc[tid] = g_ldec[(size_t)(tglob + tid) * NHEADS + h];
    for (int i = tid; i < CHUNK * HEADDIM; i += 256) {
        const int s = i >> 7, p = i & 127;
        sXsT[p * 68 + s] = f2tf32f(g_xst[xbase + i]);
    }
    for (int i = tid; i < 4096; i += 256) {
        const int s = i >> 6, n = i & 63;
        const float bv = g_Bc[(size_t)(tglob + s) * D_STATE + n];
        const float cv = g_Cc[(size_t)(tglob + s) * D_STATE + n];
        sB [s * 68 + n] = f2tf32f(bv);
        sBT[n * 68 + s] = bv;
        sC [s * 68 + n] = f2tf32f(cv);
    }
    __syncthreads();

    if (wid == 0) {
        const float e0 = sLc[2 * lane], e1 = sLc[2 * lane + 1];
        float v = e0 + e1;
#pragma unroll
        for (int ofs = 1; ofs < 32; ofs <<= 1) {
            const float o = __shfl_up_sync(0xffffffffu, v, ofs);
            if (lane >= ofs) v += o;
        }
        sLc[2 * lane]     = v - e1;
        sLc[2 * lane + 1] = v;
    }

    const uint32_t* uXsT = (const uint32_t*)sXsT;
    const uint32_t* uC   = (const uint32_t*)sC;
    const uint32_t* uB   = (const uint32_t*)sB;
    const uint32_t* uBT  = (const uint32_t*)sBT;
    const uint32_t* uG   = (const uint32_t*)sG;

    float accS[2][2][4];
#pragma unroll
    for (int mt = 0; mt < 2; mt++)
#pragma unroll
        for (int nt = 0; nt < 2; nt++)
#pragma unroll
            for (int r = 0; r < 4; r++) accS[mt][nt][r] = 0.f;

    const int smb = (wid & 1) * 32;
    const int snb = (wid >> 1) * 16;
#pragma unroll
    for (int ks = 0; ks < 8; ks++) {
        const int kc = ks * 8 + (lane & 3);
        uint32_t af[2][4];
#pragma unroll
        for (int mt = 0; mt < 2; mt++) {
            const int r = smb + mt * 16 + (lane >> 2);
            af[mt][0] = uC[r * 68 + kc];
            af[mt][1] = uC[(r + 8) * 68 + kc];
            af[mt][2] = uC[r * 68 + kc + 4];
            af[mt][3] = uC[(r + 8) * 68 + kc + 4];
        }
#pragma unroll
        for (int nt = 0; nt < 2; nt++) {
            const int rn = snb + nt * 8 + (lane >> 2);
            const uint32_t b0 = uB[rn * 68 + kc];
            const uint32_t b1 = uB[rn * 68 + kc + 4];
#pragma unroll
            for (int mt = 0; mt < 2; mt++)
                mma_tf32(accS[mt][nt], af[mt], b0, b1);
        }
    }
    __syncthreads();

#pragma unroll
    for (int mt = 0; mt < 2; mt++)
#pragma unroll
        for (int nt = 0; nt < 2; nt++)
#pragma unroll
            for (int r = 0; r < 4; r++) {
                const int t = smb + mt * 16 + (lane >> 2) + ((r >> 1) ? 8 : 0);
                const int s = snb + nt * 8 + (lane & 3) * 2 + (r & 1);
                const float gg = (s <= t)
                    ? __expf(sLc[t] - sLc[s]) * accS[mt][nt][r] : 0.f;
                sG[t * 68 + s] = f2tf32f(gg);
            }
    if (tid < 64) {
        sW[tid] = __expf(sLc[63] - sLc[tid]);
        g_lcum[(size_t)bh * T_SZ + c * CHUNK + tid] = sLc[tid];
    }
    __syncthreads();

    for (int i = tid; i < 4096; i += 256) {
        const int n = i >> 6, s = i & 63;
        sBT[n * 68 + s] = f2tf32f(sBT[n * 68 + s] * sW[s]);
    }
    __syncthreads();

    float accY[2][4][4], accH[2][4][4];
#pragma unroll
    for (int mt = 0; mt < 2; mt++)
#pragma unroll
        for (int nt = 0; nt < 4; nt++)
#pragma unroll
            for (int r = 0; r < 4; r++) { accY[mt][nt][r] = 0.f; accH[mt][nt][r] = 0.f; }

    const int pb = (wid & 3) * 32;
    const int tb = (wid >> 2) * 32;
#pragma unroll
    for (int ks = 0; ks < 8; ks++) {
        const int kc = ks * 8 + (lane & 3);
        uint32_t af[2][4];
#pragma unroll
        for (int mt = 0; mt < 2; mt++) {
            const int r = pb + mt * 16 + (lane >> 2);
            af[mt][0] = uXsT[r * 68 + kc];
            af[mt][1] = uXsT[(r + 8) * 68 + kc];
            af[mt][2] = uXsT[r * 68 + kc + 4];
            af[mt][3] = uXsT[(r + 8) * 68 + kc + 4];
        }
#pragma unroll
        for (int nt = 0; nt < 4; nt++) {
            const int rn = tb + nt * 8 + (lane >> 2);
            const uint32_t gy0 = uG [rn * 68 + kc];
            const uint32_t gy1 = uG [rn * 68 + kc + 4];
            const uint32_t bb0 = uBT[rn * 68 + kc];
            const uint32_t bb1 = uBT[rn * 68 + kc + 4];
#pragma unroll
            for (int mt = 0; mt < 2; mt++) {
                mma_tf32(accY[mt][nt], af[mt], gy0, gy1);
                mma_tf32(accH[mt][nt], af[mt], bb0, bb1);
            }
        }
    }

    const size_t hbase = ((size_t)(bh * NCHUNK + c)) * (HEADDIM * D_STATE);
#pragma unroll
    for (int mt = 0; mt < 2; mt++) {
        const int p0 = pb + mt * 16 + (lane >> 2);
#pragma unroll
        for (int nt = 0; nt < 4; nt++) {
            const int tn = tb + nt * 8 + (lane & 3) * 2;
            float* y0 = g_yint + ((size_t)bh * HEADDIM + p0) * T_SZ + c * CHUNK + tn;
            *(float2*)y0              = make_float2(accY[mt][nt][0], accY[mt][nt][1]);
            *(float2*)(y0 + 8 * T_SZ) = make_float2(accY[mt][nt][2], accY[mt][nt][3]);
            float* d0 = g_dH + hbase + (size_t)p0 * D_STATE + tn;
            *(float2*)d0                 = make_float2(accH[mt][nt][0], accH[mt][nt][1]);
            *(float2*)(d0 + 8 * D_STATE) = make_float2(accH[mt][nt][2], accH[mt][nt][3]);
        }
    }
}

// ---------------------------------------------------------------------------
// Pass 2: chunk-state recurrence, element-parallel (exact R12 body).
// ---------------------------------------------------------------------------
__global__ void __launch_bounds__(256)
chunk_state_par(const float* __restrict__ H0, float* __restrict__ Hout, int writeH)
{
    const int gtid = blockIdx.x * 256 + threadIdx.x;   // 0..131071
    const int bh   = gtid >> 10;
    const int rem  = gtid & 1023;
    const size_t eoff = (size_t)rem * 8;

    float4 Ha = *(const float4*)(H0 + (size_t)bh * (HEADDIM * D_STATE) + eoff);
    float4 Hb = *(const float4*)(H0 + (size_t)bh * (HEADDIM * D_STATE) + eoff + 4);

    for (int c = 0; c < NCHUNK; c++) {
        const size_t base = ((size_t)(bh * NCHUNK + c)) * (HEADDIM * D_STATE) + eoff;
        *(float4*)(g_Hc + base)     = Ha;
        *(float4*)(g_Hc + base + 4) = Hb;
        const float a = __expf(g_lcum[(size_t)bh * T_SZ + c * CHUNK + 63]);
        const float4 da = *(const float4*)(g_dH + base);
        const float4 db = *(const float4*)(g_dH + base + 4);
        Ha.x = a * Ha.x + da.x;  Ha.y = a * Ha.y + da.y;
        Ha.z = a * Ha.z + da.z;  Ha.w = a * Ha.w + da.w;
        Hb.x = a * Hb.x + db.x;  Hb.y = a * Hb.y + db.y;
        Hb.z = a * Hb.z + db.z;  Hb.w = a * Hb.w + db.w;
    }

    if (writeH) {
        *(float4*)(Hout + (size_t)bh * (HEADDIM * D_STATE) + eoff)     = Ha;
        *(float4*)(Hout + (size_t)bh * (HEADDIM * D_STATE) + eoff + 4) = Hb;
    }
}

// ---------------------------------------------------------------------------
// Pass 3: inter-chunk Y + gate. R12 structure (8x4 thread tile) with sH
// stride 65 -> 68 and the 8 broadcast H-loads vectorized to 2x LDS.128 per
// 4-n group. Accumulation order (n ascending) unchanged -> bit-identical.
// ---------------------------------------------------------------------------
#define INTER_SMEM ((128 * 68 + 64 * 65 + 64) * 4)   // 51712 bytes

__global__ void __launch_bounds__(256)
chunk_inter(float* __restrict__ ys)
{
    extern __shared__ float sm[];
    float* sH  = sm;                 // [128][68]  (16B-aligned rows)
    float* sC3 = sm + 128 * 68;      // [64][65]
    float* sP  = sC3 + 64 * 65;      // [64]

    const int blk = blockIdx.x;
    const int bh  = blk >> 4;
    const int c   = blk & 15;
    const int b   = bh >> 4;
    const int h   = bh & 15;
    const int tid = threadIdx.x;
    const int tx  = tid & 15;
    const int ty  = tid >> 4;

    const int tglob = b * T_SZ + c * CHUNK;

    {
        const float* src = g_Hc + ((size_t)(bh * NCHUNK + c)) * (HEADDIM * D_STATE);
        for (int i = tid; i < 8192; i += 256) {
            const int p = i >> 6, n = i & 63;
            sH[p * 68 + n] = src[i];
        }
    }
    for (int i = tid; i < 4096; i += 256) {
        const int s = i >> 6, n = i & 63;
        sC3[s * 65 + n] = g_Cc[(size_t)(tglob + s) * D_STATE + n];
    }
    if (tid < 64)
        sP[tid] = __expf(g_lcum[(size_t)bh * T_SZ + c * CHUNK + tid]);
    __syncthreads();

    float acc[8][4];
#pragma unroll
    for (int i = 0; i < 8; i++)
#pragma unroll
        for (int j = 0; j < 4; j++) acc[i][j] = 0.f;

    for (int n0 = 0; n0 < 64; n0 += 4) {
        float4 h4[8];
#pragma unroll
        for (int i = 0; i < 8; i++)
            h4[i] = *(const float4*)&sH[(ty * 8 + i) * 68 + n0];
        float cr[4][4];
#pragma unroll
        for (int nn = 0; nn < 4; nn++)
#pragma unroll
            for (int j = 0; j < 4; j++)
                cr[nn][j] = sC3[(tx * 4 + j) * 65 + n0 + nn];
#pragma unroll
        for (int nn = 0; nn < 4; nn++)
#pragma unroll
            for (int i = 0; i < 8; i++)
#pragma unroll
                for (int j = 0; j < 4; j++)
                    acc[i][j] += ((const float*)&h4[i])[nn] * cr[nn][j];
    }

    float4 yr[8];
#pragma unroll
    for (int i = 0; i < 8; i++)
        yr[i] = *(const float4*)(g_yint + ((size_t)bh * HEADDIM + ty * 8 + i) * T_SZ
                                 + c * CHUNK + tx * 4);

#pragma unroll
    for (int j = 0; j < 4; j++) {
        const int tl = tx * 4 + j;
        const size_t trow = (size_t)bh * T_SZ + c * CHUNK + tl;
        const float P = sP[tl];
        const float* zz = g_zt + trow * HEADDIM + ty * 8;
        float4 z0 = *(const float4*)(zz);
        float4 z1 = *(const float4*)(zz + 4);
        float zv[8] = { z0.x, z0.y, z0.z, z0.w, z1.x, z1.y, z1.z, z1.w };
        uint32_t ov[8];
#pragma unroll
        for (int i = 0; i < 8; i++) {
            const float yintra = ((const float*)&yr[i])[j];
            const float y  = yintra + P * acc[i][j];
            const float zy = zv[i] + y;
            ov[i] = f2tf32(y * (zy / (1.f + __expf(-zy))));
        }
        float* dst = ys + ((size_t)(b * T_SZ + c * CHUNK + tl)) * D_INNER
                        + h * HEADDIM + ty * 8;
        *(float4*)(dst) = make_float4(__uint_as_float(ov[0]), __uint_as_float(ov[1]),
                                      __uint_as_float(ov[2]), __uint_as_float(ov[3]));
        *(float4*)(dst + 4) = make_float4(__uint_as_float(ov[4]), __uint_as_float(ov[5]),
                                          __uint_as_float(ov[6]), __uint_as_float(ov[7]));
    }
}

// ---------------------------------------------------------------------------
extern "C" void kernel_launch(void* const* d_in, const int* in_sizes, int n_in,
                              void* d_out, int out_size)
{
    const float* x       = (const float*)d_in[0];
    const float* H0      = (const float*)d_in[1];
    const float* W_in    = (const float*)d_in[2];
    const float* W_out   = (const float*)d_in[3];
    const float* dt_bias = (const float*)d_in[4];
    float* out = (float*)d_out;

    static float *ys_p = nullptr, *xr_p = nullptr, *wir_p = nullptr, *wor_p = nullptr;
    if (!ys_p) {
        cudaGetSymbolAddress((void**)&ys_p,  g_ys);
        cudaGetSymbolAddress((void**)&xr_p,  g_xr);
        cudaGetSymbolAddress((void**)&wir_p, g_wir);
        cudaGetSymbolAddress((void**)&wor_p, g_wor);
        cudaFuncSetAttribute(gemm_tf32,
                             cudaFuncAttributeMaxDynamicSharedMemorySize, GSMEM_BYTES);
        cudaFuncSetAttribute(chunk_intra,
                             cudaFuncAttributeMaxDynamicSharedMemorySize, 104960);
        cudaFuncSetAttribute(chunk_inter,
                             cudaFuncAttributeMaxDynamicSharedMemorySize, INTER_SMEM);
    }

    const int out_elems = B_SZ * T_SZ * DIM;
    const int h_elems   = B_SZ * NHEADS * HEADDIM * D_STATE;
    const int writeH    = (out_size >= out_elems + h_elems) ? 1 : 0;
    float* Hout = out + out_elems;

    // 0) tf32-round all GEMM inputs (one launch)
    round_all<<<2048, 256>>>(x, xr_p, M_TOK * DIM,
                             W_in, wir_p, D_PROJ * DIM,
                             W_out, wor_p, DIM * D_INNER);

    // 1) proj GEMM with fused scatter epilogue
    gemm_tf32<<<dim3((D_PROJ + 127) / 128, M_TOK / 128), 256, GSMEM_BYTES>>>(
        xr_p, wir_p, nullptr, M_TOK, D_PROJ, DIM, 0, 1, dt_bias);

    // 2) chunked scan
    chunk_intra<<<NBH * NCHUNK, 256, 104960>>>();
    chunk_state_par<<<512, 256>>>(H0, Hout, writeH);
    chunk_inter<<<NBH * NCHUNK, 256, INTER_SMEM>>>(ys_p);

    // 3) output = ys @ W_out^T
    gemm_tf32<<<dim3(DIM / 128, M_TOK / 128), 256, GSMEM_BYTES>>>(
        ys_p, wor_p, out, M_TOK, DIM, D_INNER, 0, 0, nullptr);
}

// round 16
// speedup vs baseline: 1.0615x; 1.0018x over previous
#include <cuda_runtime.h>
#include <cuda_bf16.h>
#include <cstdint>

#define DIM      1024
#define D_INNER  2048
#define NHEADS   16
#define HEADDIM  128
#define D_STATE  64
#define D_PROJ   4240   // 2*D_INNER + 2*D_STATE + NHEADS
#define B_SZ     8
#define T_SZ     1024
#define M_TOK    (B_SZ * T_SZ)   // 8192
#define NBH      (B_SZ * NHEADS) // 128
#define CHUNK    64
#define NCHUNK   (T_SZ / CHUNK)  // 16

// ---------------------------------------------------------------------------
// Scratch (no cudaMalloc allowed): device globals.
// ---------------------------------------------------------------------------
__device__ float g_ys[(size_t)M_TOK * D_INNER];            // final gated ys (tf32)
__device__ float g_xr[(size_t)M_TOK * DIM];                // x tf32-rounded
__device__ float g_wir[(size_t)D_PROJ * DIM];              // W_in rounded
__device__ float g_wor[(size_t)DIM * D_INNER];             // W_out rounded
__device__ float g_xst[(size_t)NBH * T_SZ * HEADDIM];      // silu(x_p) [bh,t,p]
__device__ float g_zt [(size_t)NBH * T_SZ * HEADDIM];      // z [bh,t,p]
__device__ float g_Bc [(size_t)M_TOK * D_STATE];           // [bt,n]
__device__ float g_Cc [(size_t)M_TOK * D_STATE];           // [bt,n]
__device__ float g_ldec[(size_t)M_TOK * NHEADS];           // log(sigmoid(dt+bias)) [bt,h]
__device__ float g_yint[(size_t)NBH * HEADDIM * T_SZ];     // intra-chunk Y TRANSPOSED [bh,p,t]
__device__ float g_dH [(size_t)NBH * NCHUNK * HEADDIM * D_STATE]; // per-chunk state delta
__device__ float g_Hc [(size_t)NBH * NCHUNK * HEADDIM * D_STATE]; // state ENTERING chunk c
__device__ float g_lcum[(size_t)NBH * T_SZ];               // within-chunk log-decay cumsum

// ---------------------------------------------------------------------------
// helpers
// ---------------------------------------------------------------------------
__device__ __forceinline__ uint32_t f2tf32(float f) {
    uint32_t u;
    asm("cvt.rna.tf32.f32 %0, %1;" : "=r"(u) : "f"(f));
    return u;
}
__device__ __forceinline__ float f2tf32f(float f) {
    return __uint_as_float(f2tf32(f));
}

__device__ __forceinline__ void cpasync16(uint32_t dst, const void* src) {
    asm volatile("cp.async.cg.shared.global [%0], [%1], 16;" :: "r"(dst), "l"(src));
}

__device__ __forceinline__ void mma_tf32(float* c, const uint32_t* a,
                                         uint32_t b0, uint32_t b1) {
    asm volatile(
        "mma.sync.aligned.m16n8k8.row.col.f32.tf32.tf32.f32 "
        "{%0,%1,%2,%3}, {%4,%5,%6,%7}, {%8,%9}, {%0,%1,%2,%3};"
        : "+f"(c[0]), "+f"(c[1]), "+f"(c[2]), "+f"(c[3])
        : "r"(a[0]), "r"(a[1]), "r"(a[2]), "r"(a[3]), "r"(b0), "r"(b1));
}

// ldmatrix: one instr loads 4 (x4) or 2 (x2) 8x8-b16 tiles == tf32 fragments
__device__ __forceinline__ void ldsm_x4(uint32_t* r, uint32_t addr) {
    asm volatile("ldmatrix.sync.aligned.m8n8.x4.shared.b16 {%0,%1,%2,%3}, [%4];"
                 : "=r"(r[0]), "=r"(r[1]), "=r"(r[2]), "=r"(r[3]) : "r"(addr));
}
__device__ __forceinline__ void ldsm_x2(uint32_t* r, uint32_t addr) {
    asm volatile("ldmatrix.sync.aligned.m8n8.x2.shared.b16 {%0,%1}, [%2];"
                 : "=r"(r[0]), "=r"(r[1]) : "r"(addr));
}

// one launch rounding all three GEMM inputs fp32 -> tf32-bits
__global__ void round_all(const float* __restrict__ s0, float* __restrict__ d0, int n0,
                          const float* __restrict__ s1, float* __restrict__ d1, int n1,
                          const float* __restrict__ s2, float* __restrict__ d2, int n2) {
    const int stride = gridDim.x * blockDim.x;
    const int t0 = blockIdx.x * blockDim.x + threadIdx.x;
    for (int i = t0; i < n0; i += stride) d0[i] = __uint_as_float(f2tf32(s0[i]));
    for (int i = t0; i < n1; i += stride) d1[i] = __uint_as_float(f2tf32(s1[i]));
    for (int i = t0; i < n2; i += stride) d2[i] = __uint_as_float(f2tf32(s2[i]));
}

// ---------------------------------------------------------------------------
// scatter epilogue for GEMM1 (mode 1): route proj columns to scan buffers.
// ---------------------------------------------------------------------------
__device__ __forceinline__ void scatter_pair(int row, int col, float v0, float v1,
                                             const float* __restrict__ dt_bias)
{
    const int b = row >> 10;
    const int t = row & 1023;
    if (col < D_INNER) {                        // x -> silu -> g_xst [bh,t,p]
        const int h = col >> 7, pp = col & 127;
        const float s0 = v0 / (1.f + __expf(-v0));
        const float s1 = v1 / (1.f + __expf(-v1));
        *(float2*)(g_xst + ((size_t)(b * NHEADS + h) * T_SZ + t) * HEADDIM + pp)
            = make_float2(s0, s1);
    } else if (col < 2 * D_INNER) {             // z -> g_zt [bh,t,p]
        const int c = col - D_INNER;
        const int h = c >> 7, pp = c & 127;
        *(float2*)(g_zt + ((size_t)(b * NHEADS + h) * T_SZ + t) * HEADDIM + pp)
            = make_float2(v0, v1);
    } else if (col < 2 * D_INNER + D_STATE) {   // B
        *(float2*)(g_Bc + (size_t)row * D_STATE + (col - 2 * D_INNER))
            = make_float2(v0, v1);
    } else if (col < 2 * D_INNER + 2 * D_STATE) { // C
        *(float2*)(g_Cc + (size_t)row * D_STATE + (col - 2 * D_INNER - D_STATE))
            = make_float2(v0, v1);
    } else {                                    // dt -> log(sigmoid(dt+bias))
        const int h = col - (2 * D_INNER + 2 * D_STATE);
        const float u0 = v0 + dt_bias[h];
        const float u1 = v1 + dt_bias[h + 1];
        g_ldec[(size_t)row * NHEADS + h]     = (u0 > -15.f) ? -log1pf(__expf(-u0)) : u0;
        g_ldec[(size_t)row * NHEADS + h + 1] = (u1 > -15.f) ? -log1pf(__expf(-u1)) : u1;
    }
}

// ---------------------------------------------------------------------------
// tf32 mma.sync GEMM (R6 tiling + ldmatrix fragment loads; exact R12 body)
// ---------------------------------------------------------------------------
#define GSMEM_BYTES 98304

__global__ void __launch_bounds__(256, 2)
gemm_tf32(const float* __restrict__ A, const float* __restrict__ W,
          float* __restrict__ C, int M, int N, int K,
          int bnOff, int mode, const float* __restrict__ dt_bias)
{
    extern __shared__ float smem[];
    const uint32_t smemAddr = (uint32_t)__cvta_generic_to_shared(smem);

    const int tid  = threadIdx.x;
    const int lane = tid & 31;
    const int wid  = tid >> 5;
    const int wm   = wid & 1;
    const int wn   = wid >> 1;

    const int bm = blockIdx.y * 128;
    const int bn = blockIdx.x * 128 + bnOff;

    const int sr   = tid >> 1;
    const int half = tid & 1;
    const float* arow = A + (size_t)(bm + sr) * K;
    const int wRow = (bn + sr) < N ? (bn + sr) : (N - 1);
    const float* wrow = W + (size_t)wRow * K;

    const int g      = lane >> 3;
    const int rIn    = lane & 7;
    const int khalfA = g >> 1;
    const int khalfB = g & 1;
    uint32_t aOff[4], aSw[4], bOff[4], bSw[4];
#pragma unroll
    for (int mt = 0; mt < 4; mt++) {
        const int r = wm * 64 + mt * 16 + (g & 1) * 8 + rIn;
        aOff[mt] = r * 128;
        aSw[mt]  = r & 7;
    }
#pragma unroll
    for (int nt = 0; nt < 4; nt++) {
        const int r = wn * 32 + nt * 8 + rIn;
        bOff[nt] = 16384 + r * 128;
        bSw[nt]  = r & 7;
    }

    float acc[4][4][4];
#pragma unroll
    for (int mt = 0; mt < 4; mt++)
#pragma unroll
        for (int nt = 0; nt < 4; nt++)
#pragma unroll
            for (int r = 0; r < 4; r++) acc[mt][nt][r] = 0.f;

    const int nk = K >> 5;

#define STAGE(bufIdx, kk)                                                     \
    do {                                                                      \
        uint32_t baseA = smemAddr + (bufIdx) * 32768 + sr * 128;              \
        uint32_t baseB = baseA + 16384;                                       \
        _Pragma("unroll")                                                     \
        for (int i = 0; i < 4; i++) {                                         \
            int ch  = half * 4 + i;                                           \
            int chs = ch ^ (sr & 7);                                          \
            cpasync16(baseA + chs * 16, arow + (kk) + ch * 4);                \
            cpasync16(baseB + chs * 16, wrow + (kk) + ch * 4);                \
        }                                                                     \
    } while (0)

    STAGE(0, 0);
    asm volatile("cp.async.commit_group;");
    if (nk > 1) STAGE(1, 32);
    asm volatile("cp.async.commit_group;");

    int bufC = 0, bufP = 2;
    for (int kt = 0; kt < nk; kt++) {
        if (kt + 2 < nk) STAGE(bufP, (kt + 2) * 32);
        asm volatile("cp.async.commit_group;");
        asm volatile("cp.async.wait_group 2;");
        __syncthreads();

        const uint32_t stageBase = smemAddr + bufC * 32768;

#pragma unroll
        for (int ks = 0; ks < 4; ks++) {
            uint32_t af[4][4], bf[4][2];
#pragma unroll
            for (int mt = 0; mt < 4; mt++) {
                const uint32_t ch = (uint32_t)(ks * 2 + khalfA) ^ aSw[mt];
                ldsm_x4(af[mt], stageBase + aOff[mt] + ch * 16);
            }
#pragma unroll
            for (int nt = 0; nt < 4; nt++) {
                const uint32_t ch = (uint32_t)(ks * 2 + khalfB) ^ bSw[nt];
                ldsm_x2(bf[nt], stageBase + bOff[nt] + ch * 16);
            }
#pragma unroll
            for (int mt = 0; mt < 4; mt++)
#pragma unroll
                for (int nt = 0; nt < 4; nt++)
                    mma_tf32(acc[mt][nt], af[mt], bf[nt][0], bf[nt][1]);
        }
        __syncthreads();
        bufC = (bufC == 2) ? 0 : bufC + 1;
        bufP = (bufP == 2) ? 0 : bufP + 1;
    }
#undef STAGE

#pragma unroll
    for (int mt = 0; mt < 4; mt++) {
        const int row0 = bm + wm * 64 + mt * 16 + (lane >> 2);
#pragma unroll
        for (int nt = 0; nt < 4; nt++) {
            const int col = bn + wn * 32 + nt * 8 + (lane & 3) * 2;
            if (col < N) {
                if (mode == 0) {
                    *(float2*)(C + (size_t)row0 * N + col)
                        = make_float2(acc[mt][nt][0], acc[mt][nt][1]);
                    *(float2*)(C + (size_t)(row0 + 8) * N + col)
                        = make_float2(acc[mt][nt][2], acc[mt][nt][3]);
                } else {
                    scatter_pair(row0,     col, acc[mt][nt][0], acc[mt][nt][1], dt_bias);
                    scatter_pair(row0 + 8, col, acc[mt][nt][2], acc[mt][nt][3], dt_bias);
                }
            }
        }
    }
}

// ---------------------------------------------------------------------------
// Pass 1 (TENSORIZED): one block per (bh, chunk) = 2048.
// Y and dH MMA passes UNFUSED (live accs 80 -> 32 regs) + launch_bounds(256,2)
// to restore 2 blocks/SM occupancy. Identical ks-ascending mma order per
// accumulator -> bit-identical results.
// ---------------------------------------------------------------------------
__global__ void __launch_bounds__(256, 2)
chunk_intra()
{
    extern __shared__ float sm[];
    float* sXsT = sm;                    // [128][68]  Xs^T[p][s]
    float* sC   = sXsT + 128 * 68;       // [64][68]   C[t][n]
    float* sB   = sC   + 64 * 68;        // [64][68]   B[s][n]   (rounded)
    float* sBT  = sB   + 64 * 68;        // [64][68]   B^T[n][s]
    float* sG   = sBT  + 64 * 68;        // [64][68]   G[t][s]
    float* sLc  = sG   + 64 * 68;        // [64]
    float* sW   = sLc  + 64;             // [64]

    const int blk  = blockIdx.x;
    const int bh   = blk >> 4;
    const int c    = blk & 15;
    const int b    = bh >> 4;
    const int h    = bh & 15;
    const int tid  = threadIdx.x;
    const int lane = tid & 31;
    const int wid  = tid >> 5;

    const int tglob = b * T_SZ + c * CHUNK;
    const size_t xbase = ((size_t)bh * T_SZ + c * CHUNK) * HEADDIM;

    if (tid < 64)
        sLc[tid] = g_ldec[(size_t)(tglob + tid) * NHEADS + h];
    for (int i = tid; i < CHUNK * HEADDIM; i += 256) {
        const int s = i >> 7, p = i & 127;
        sXsT[p * 68 + s] = f2tf32f(g_xst[xbase + i]);
    }
    for (int i = tid; i < 4096; i += 256) {
        const int s = i >> 6, n = i & 63;
        const float bv = g_Bc[(size_t)(tglob + s) * D_STATE + n];
        const float cv = g_Cc[(size_t)(tglob + s) * D_STATE + n];
        sB [s * 68 + n] = f2tf32f(bv);
        sBT[n * 68 + s] = bv;
        sC [s * 68 + n] = f2tf32f(cv);
    }
    __syncthreads();

    if (wid == 0) {
        const float e0 = sLc[2 * lane], e1 = sLc[2 * lane + 1];
        float v = e0 + e1;
#pragma unroll
        for (int ofs = 1; ofs < 32; ofs <<= 1) {
            const float o = __shfl_up_sync(0xffffffffu, v, ofs);
            if (lane >= ofs) v += o;
        }
        sLc[2 * lane]     = v - e1;
        sLc[2 * lane + 1] = v;
    }

    const uint32_t* uXsT = (const uint32_t*)sXsT;
    const uint32_t* uC   = (const uint32_t*)sC;
    const uint32_t* uB   = (const uint32_t*)sB;
    const uint32_t* uBT  = (const uint32_t*)sBT;
    const uint32_t* uG   = (const uint32_t*)sG;

    // ---- S = C.B^T ----
    {
        float accS[2][2][4];
#pragma unroll
        for (int mt = 0; mt < 2; mt++)
#pragma unroll
            for (int nt = 0; nt < 2; nt++)
#pragma unroll
                for (int r = 0; r < 4; r++) accS[mt][nt][r] = 0.f;

        const int smb = (wid & 1) * 32;
        const int snb = (wid >> 1) * 16;
#pragma unroll
        for (int ks = 0; ks < 8; ks++) {
            const int kc = ks * 8 + (lane & 3);
            uint32_t af[2][4];
#pragma unroll
            for (int mt = 0; mt < 2; mt++) {
                const int r = smb + mt * 16 + (lane >> 2);
                af[mt][0] = uC[r * 68 + kc];
                af[mt][1] = uC[(r + 8) * 68 + kc];
                af[mt][2] = uC[r * 68 + kc + 4];
                af[mt][3] = uC[(r + 8) * 68 + kc + 4];
            }
#pragma unroll
            for (int nt = 0; nt < 2; nt++) {
                const int rn = snb + nt * 8 + (lane >> 2);
                const uint32_t b0 = uB[rn * 68 + kc];
                const uint32_t b1 = uB[rn * 68 + kc + 4];
#pragma unroll
                for (int mt = 0; mt < 2; mt++)
                    mma_tf32(accS[mt][nt], af[mt], b0, b1);
            }
        }
        __syncthreads();

#pragma unroll
        for (int mt = 0; mt < 2; mt++)
#pragma unroll
            for (int nt = 0; nt < 2; nt++)
#pragma unroll
                for (int r = 0; r < 4; r++) {
                    const int t = smb + mt * 16 + (lane >> 2) + ((r >> 1) ? 8 : 0);
                    const int s = snb + nt * 8 + (lane & 3) * 2 + (r & 1);
                    const float gg = (s <= t)
                        ? __expf(sLc[t] - sLc[s]) * accS[mt][nt][r] : 0.f;
                    sG[t * 68 + s] = f2tf32f(gg);
                }
    }
    if (tid < 64) {
        sW[tid] = __expf(sLc[63] - sLc[tid]);
        g_lcum[(size_t)bh * T_SZ + c * CHUNK + tid] = sLc[tid];
    }
    __syncthreads();

    for (int i = tid; i < 4096; i += 256) {
        const int n = i >> 6, s = i & 63;
        sBT[n * 68 + s] = f2tf32f(sBT[n * 68 + s] * sW[s]);
    }
    __syncthreads();

    const int pb = (wid & 3) * 32;
    const int tb = (wid >> 2) * 32;

    // ---- Y^T = Xs^T . G^T (pass 1 of 2) ----
    {
        float accY[2][4][4];
#pragma unroll
        for (int mt = 0; mt < 2; mt++)
#pragma unroll
            for (int nt = 0; nt < 4; nt++)
#pragma unroll
                for (int r = 0; r < 4; r++) accY[mt][nt][r] = 0.f;

#pragma unroll
        for (int ks = 0; ks < 8; ks++) {
            const int kc = ks * 8 + (lane & 3);
            uint32_t af[2][4];
#pragma unroll
            for (int mt = 0; mt < 2; mt++) {
                const int r = pb + mt * 16 + (lane >> 2);
                af[mt][0] = uXsT[r * 68 + kc];
                af[mt][1] = uXsT[(r + 8) * 68 + kc];
                af[mt][2] = uXsT[r * 68 + kc + 4];
                af[mt][3] = uXsT[(r + 8) * 68 + kc + 4];
            }
#pragma unroll
            for (int nt = 0; nt < 4; nt++) {
                const int rn = tb + nt * 8 + (lane >> 2);
                const uint32_t gy0 = uG[rn * 68 + kc];
                const uint32_t gy1 = uG[rn * 68 + kc + 4];
#pragma unroll
                for (int mt = 0; mt < 2; mt++)
                    mma_tf32(accY[mt][nt], af[mt], gy0, gy1);
            }
        }
#pragma unroll
        for (int mt = 0; mt < 2; mt++) {
            const int p0 = pb + mt * 16 + (lane >> 2);
#pragma unroll
            for (int nt = 0; nt < 4; nt++) {
                const int tn = tb + nt * 8 + (lane & 3) * 2;
                float* y0 = g_yint + ((size_t)bh * HEADDIM + p0) * T_SZ + c * CHUNK + tn;
                *(float2*)y0              = make_float2(accY[mt][nt][0], accY[mt][nt][1]);
                *(float2*)(y0 + 8 * T_SZ) = make_float2(accY[mt][nt][2], accY[mt][nt][3]);
            }
        }
    }

    // ---- dH = Xs^T . Bw^T (pass 2 of 2) ----
    {
        float accH[2][4][4];
#pragma unroll
        for (int mt = 0; mt < 2; mt++)
#pragma unroll
            for (int nt = 0; nt < 4; nt++)
#pragma unroll
                for (int r = 0; r < 4; r++) accH[mt][nt][r] = 0.f;

#pragma unroll
        for (int ks = 0; ks < 8; ks++) {
            const int kc = ks * 8 + (lane & 3);
            uint32_t af[2][4];
#pragma unroll
            for (int mt = 0; mt < 2; mt++) {
                const int r = pb + mt * 16 + (lane >> 2);
                af[mt][0] = uXsT[r * 68 + kc];
                af[mt][1] = uXsT[(r + 8) * 68 + kc];
                af[mt][2] = uXsT[r * 68 + kc + 4];
                af[mt][3] = uXsT[(r + 8) * 68 + kc + 4];
            }
#pragma unroll
            for (int nt = 0; nt < 4; nt++) {
                const int rn = tb + nt * 8 + (lane >> 2);
                const uint32_t bb0 = uBT[rn * 68 + kc];
                const uint32_t bb1 = uBT[rn * 68 + kc + 4];
#pragma unroll
                for (int mt = 0; mt < 2; mt++)
                    mma_tf32(accH[mt][nt], af[mt], bb0, bb1);
            }
        }
        const size_t hbase = ((size_t)(bh * NCHUNK + c)) * (HEADDIM * D_STATE);
#pragma unroll
        for (int mt = 0; mt < 2; mt++) {
            const int p0 = pb + mt * 16 + (lane >> 2);
#pragma unroll
            for (int nt = 0; nt < 4; nt++) {
                const int tn = tb + nt * 8 + (lane & 3) * 2;
                float* d0 = g_dH + hbase + (size_t)p0 * D_STATE + tn;
                *(float2*)d0                 = make_float2(accH[mt][nt][0], accH[mt][nt][1]);
                *(float2*)(d0 + 8 * D_STATE) = make_float2(accH[mt][nt][2], accH[mt][nt][3]);
            }
        }
    }
}

// ---------------------------------------------------------------------------
// Pass 2: chunk-state recurrence, element-parallel. Finer split than R12:
// 1024 blocks, one float4 per thread (2048 threads per bh). Same per-element
// op order -> bit-identical.
// ---------------------------------------------------------------------------
__global__ void __launch_bounds__(256)
chunk_state_par(const float* __restrict__ H0, float* __restrict__ Hout, int writeH)
{
    const int gtid = blockIdx.x * 256 + threadIdx.x;   // 0..262143
    const int bh   = gtid >> 11;                       // 2048 threads per bh
    const int rem  = gtid & 2047;
    const size_t eoff = (size_t)rem * 4;

    float4 Ha = *(const float4*)(H0 + (size_t)bh * (HEADDIM * D_STATE) + eoff);

    for (int c = 0; c < NCHUNK; c++) {
        const size_t base = ((size_t)(bh * NCHUNK + c)) * (HEADDIM * D_STATE) + eoff;
        *(float4*)(g_Hc + base) = Ha;
        const float a = __expf(g_lcum[(size_t)bh * T_SZ + c * CHUNK + 63]);
        const float4 da = *(const float4*)(g_dH + base);
        Ha.x = a * Ha.x + da.x;  Ha.y = a * Ha.y + da.y;
        Ha.z = a * Ha.z + da.z;  Ha.w = a * Ha.w + da.w;
    }

    if (writeH)
        *(float4*)(Hout + (size_t)bh * (HEADDIM * D_STATE) + eoff) = Ha;
}

// ---------------------------------------------------------------------------
// Pass 3: inter-chunk Y + gate (exact R15 body).
// ---------------------------------------------------------------------------
#define INTER_SMEM ((128 * 68 + 64 * 65 + 64) * 4)   // 51712 bytes

__global__ void __launch_bounds__(256)
chunk_inter(float* __restrict__ ys)
{
    extern __shared__ float sm[];
    float* sH  = sm;                 // [128][68]  (16B-aligned rows)
    float* sC3 = sm + 128 * 68;      // [64][65]
    float* sP  = sC3 + 64 * 65;      // [64]

    const int blk = blockIdx.x;
    const int bh  = blk >> 4;
    const int c   = blk & 15;
    const int b   = bh >> 4;
    const int h   = bh & 15;
    const int tid = threadIdx.x;
    const int tx  = tid & 15;
    const int ty  = tid >> 4;

    const int tglob = b * T_SZ + c * CHUNK;

    {
        const float* src = g_Hc + ((size_t)(bh * NCHUNK + c)) * (HEADDIM * D_STATE);
        for (int i = tid; i < 8192; i += 256) {
            const int p = i >> 6, n = i & 63;
            sH[p * 68 + n] = src[i];
        }
    }
    for (int i = tid; i < 4096; i += 256) {
        const int s = i >> 6, n = i & 63;
        sC3[s * 65 + n] = g_Cc[(size_t)(tglob + s) * D_STATE + n];
    }
    if (tid < 64)
        sP[tid] = __expf(g_lcum[(size_t)bh * T_SZ + c * CHUNK + tid]);
    __syncthreads();

    float acc[8][4];
#pragma unroll
    for (int i = 0; i < 8; i++)
#pragma unroll
        for (int j = 0; j < 4; j++) acc[i][j] = 0.f;

    for (int n0 = 0; n0 < 64; n0 += 4) {
        float4 h4[8];
#pragma unroll
        for (int i = 0; i < 8; i++)
            h4[i] = *(const float4*)&sH[(ty * 8 + i) * 68 + n0];
        float cr[4][4];
#pragma unroll
        for (int nn = 0; nn < 4; nn++)
#pragma unroll
            for (int j = 0; j < 4; j++)
                cr[nn][j] = sC3[(tx * 4 + j) * 65 + n0 + nn];
#pragma unroll
        for (int nn = 0; nn < 4; nn++)
#pragma unroll
            for (int i = 0; i < 8; i++)
#pragma unroll
                for (int j = 0; j < 4; j++)
                    acc[i][j] += ((const float*)&h4[i])[nn] * cr[nn][j];
    }

    float4 yr[8];
#pragma unroll
    for (int i = 0; i < 8; i++)
        yr[i] = *(const float4*)(g_yint + ((size_t)bh * HEADDIM + ty * 8 + i) * T_SZ
                                 + c * CHUNK + tx * 4);

#pragma unroll
    for (int j = 0; j < 4; j++) {
        const int tl = tx * 4 + j;
        const size_t trow = (size_t)bh * T_SZ + c * CHUNK + tl;
        const float P = sP[tl];
        const float* zz = g_zt + trow * HEADDIM + ty * 8;
        float4 z0 = *(const float4*)(zz);
        float4 z1 = *(const float4*)(zz + 4);
        float zv[8] = { z0.x, z0.y, z0.z, z0.w, z1.x, z1.y, z1.z, z1.w };
        uint32_t ov[8];
#pragma unroll
        for (int i = 0; i < 8; i++) {
            const float yintra = ((const float*)&yr[i])[j];
            const float y  = yintra + P * acc[i][j];
            const float zy = zv[i] + y;
            ov[i] = f2tf32(y * (zy / (1.f + __expf(-zy))));
        }
        float* dst = ys + ((size_t)(b * T_SZ + c * CHUNK + tl)) * D_INNER
                        + h * HEADDIM + ty * 8;
        *(float4*)(dst) = make_float4(__uint_as_float(ov[0]), __uint_as_float(ov[1]),
                                      __uint_as_float(ov[2]), __uint_as_float(ov[3]));
        *(float4*)(dst + 4) = make_float4(__uint_as_float(ov[4]), __uint_as_float(ov[5]),
                                          __uint_as_float(ov[6]), __uint_as_float(ov[7]));
    }
}

// ---------------------------------------------------------------------------
extern "C" void kernel_launch(void* const* d_in, const int* in_sizes, int n_in,
                              void* d_out, int out_size)
{
    const float* x       = (const float*)d_in[0];
    const float* H0      = (const float*)d_in[1];
    const float* W_in    = (const float*)d_in[2];
    const float* W_out   = (const float*)d_in[3];
    const float* dt_bias = (const float*)d_in[4];
    float* out = (float*)d_out;

    static float *ys_p = nullptr, *xr_p = nullptr, *wir_p = nullptr, *wor_p = nullptr;
    if (!ys_p) {
        cudaGetSymbolAddress((void**)&ys_p,  g_ys);
        cudaGetSymbolAddress((void**)&xr_p,  g_xr);
        cudaGetSymbolAddress((void**)&wir_p, g_wir);
        cudaGetSymbolAddress((void**)&wor_p, g_wor);
        cudaFuncSetAttribute(gemm_tf32,
                             cudaFuncAttributeMaxDynamicSharedMemorySize, GSMEM_BYTES);
        cudaFuncSetAttribute(chunk_intra,
                             cudaFuncAttributeMaxDynamicSharedMemorySize, 104960);
        cudaFuncSetAttribute(chunk_inter,
                             cudaFuncAttributeMaxDynamicSharedMemorySize, INTER_SMEM);
    }

    const int out_elems = B_SZ * T_SZ * DIM;
    const int h_elems   = B_SZ * NHEADS * HEADDIM * D_STATE;
    const int writeH    = (out_size >= out_elems + h_elems) ? 1 : 0;
    float* Hout = out + out_elems;

    // 0) tf32-round all GEMM inputs (one launch)
    round_all<<<2048, 256>>>(x, xr_p, M_TOK * DIM,
                             W_in, wir_p, D_PROJ * DIM,
                             W_out, wor_p, DIM * D_INNER);

    // 1) proj GEMM with fused scatter epilogue
    gemm_tf32<<<dim3((D_PROJ + 127) / 128, M_TOK / 128), 256, GSMEM_BYTES>>>(
        xr_p, wir_p, nullptr, M_TOK, D_PROJ, DIM, 0, 1, dt_bias);

    // 2) chunked scan
    chunk_intra<<<NBH * NCHUNK, 256, 104960>>>();
    chunk_state_par<<<1024, 256>>>(H0, Hout, writeH);
    chunk_inter<<<NBH * NCHUNK, 256, INTER_SMEM>>>(ys_p);

    // 3) output = ys @ W_out^T
    gemm_tf32<<<dim3(DIM / 128, M_TOK / 128), 256, GSMEM_BYTES>>>(
        ys_p, wor_p, out, M_TOK, DIM, D_INNER, 0, 0, nullptr);
}